// round 2
// baseline (speedup 1.0000x reference)
#include <cuda_runtime.h>
#include <cuda_bf16.h>

#define NN 100000
#define EE 1600000
#define IND 128
#define HID 64

// scratch (static device globals; allocation-free)
__device__ float g_ft[NN * HID];
__device__ float g_res[NN * HID];
__device__ float g_sdst[NN];
__device__ float g_ssrc[NN];
__device__ float g_score[EE];
__device__ int   g_rowptr[NN + 1];
__device__ float g_wl[HID];
__device__ float g_wr[HID];

// ---------------------------------------------------------------------------
// wl_vec[h] = sum_a W_l[h][a]   (since (ft@W_l).sum(-1) == ft @ W_l.sum(axis=1))
__global__ void k_vec(const float* __restrict__ Wl, const float* __restrict__ Wr) {
    int t = threadIdx.x;  // 64 threads
    float sl = 0.f, sr = 0.f;
#pragma unroll
    for (int a = 0; a < 64; a++) {
        sl += Wl[t * 64 + a];
        sr += Wr[t * 64 + a];
    }
    g_wl[t] = sl;
    g_wr[t] = sr;
}

// ---------------------------------------------------------------------------
// Fused double GEMM: ft = feats@W_fc, res = feats@W_res (shared A fragments),
// plus epilogue s_dst = ft.wl, s_src = ft.wr via shared-mem reduction.
// Tile: 64 rows x 64 cols, K-chunks of 32; 256 threads, 4x4 per thread per matrix.
__global__ void __launch_bounds__(256) k_gemm(const float* __restrict__ feats,
                                              const float* __restrict__ Wfc,
                                              const float* __restrict__ Wres) {
    __shared__ float As[64][33];
    __shared__ float Bf[32][64];
    __shared__ float Br[32][64];
    __shared__ float ssl[64];
    __shared__ float ssr[64];

    int tid = threadIdx.x;
    int row0 = blockIdx.x * 64;
    if (tid < 64) { ssl[tid] = 0.f; ssr[tid] = 0.f; }

    float accF[4][4] = {};
    float accR[4][4] = {};
    int rb = (tid >> 4) << 2;   // 0..60
    int cb = (tid & 15) << 2;   // 0..60

    for (int k0 = 0; k0 < IND; k0 += 32) {
        __syncthreads();
#pragma unroll
        for (int i = 0; i < 8; i++) {
            int idx = tid + i * 256;
            int r = idx >> 5, kk = idx & 31;
            int gr = row0 + r;
            As[r][kk] = (gr < NN) ? feats[gr * IND + k0 + kk] : 0.f;
        }
#pragma unroll
        for (int i = 0; i < 8; i++) {
            int idx = tid + i * 256;
            int kk = idx >> 6, c = idx & 63;
            Bf[kk][c] = Wfc[(k0 + kk) * 64 + c];
            Br[kk][c] = Wres[(k0 + kk) * 64 + c];
        }
        __syncthreads();
#pragma unroll
        for (int kk = 0; kk < 32; kk++) {
            float a0 = As[rb + 0][kk];
            float a1 = As[rb + 1][kk];
            float a2 = As[rb + 2][kk];
            float a3 = As[rb + 3][kk];
            float4 bf = *(const float4*)&Bf[kk][cb];
            float4 br = *(const float4*)&Br[kk][cb];
            accF[0][0] += a0 * bf.x; accF[0][1] += a0 * bf.y; accF[0][2] += a0 * bf.z; accF[0][3] += a0 * bf.w;
            accF[1][0] += a1 * bf.x; accF[1][1] += a1 * bf.y; accF[1][2] += a1 * bf.z; accF[1][3] += a1 * bf.w;
            accF[2][0] += a2 * bf.x; accF[2][1] += a2 * bf.y; accF[2][2] += a2 * bf.z; accF[2][3] += a2 * bf.w;
            accF[3][0] += a3 * bf.x; accF[3][1] += a3 * bf.y; accF[3][2] += a3 * bf.z; accF[3][3] += a3 * bf.w;
            accR[0][0] += a0 * br.x; accR[0][1] += a0 * br.y; accR[0][2] += a0 * br.z; accR[0][3] += a0 * br.w;
            accR[1][0] += a1 * br.x; accR[1][1] += a1 * br.y; accR[1][2] += a1 * br.z; accR[1][3] += a1 * br.w;
            accR[2][0] += a2 * br.x; accR[2][1] += a2 * br.y; accR[2][2] += a2 * br.z; accR[2][3] += a2 * br.w;
            accR[3][0] += a3 * br.x; accR[3][1] += a3 * br.y; accR[3][2] += a3 * br.z; accR[3][3] += a3 * br.w;
        }
    }

    float wl0 = g_wl[cb + 0], wl1 = g_wl[cb + 1], wl2 = g_wl[cb + 2], wl3 = g_wl[cb + 3];
    float wr0 = g_wr[cb + 0], wr1 = g_wr[cb + 1], wr2 = g_wr[cb + 2], wr3 = g_wr[cb + 3];

#pragma unroll
    for (int i = 0; i < 4; i++) {
        int gr = row0 + rb + i;
        if (gr < NN) {
            *(float4*)&g_ft[gr * 64 + cb]  = make_float4(accF[i][0], accF[i][1], accF[i][2], accF[i][3]);
            *(float4*)&g_res[gr * 64 + cb] = make_float4(accR[i][0], accR[i][1], accR[i][2], accR[i][3]);
            float pl = accF[i][0] * wl0 + accF[i][1] * wl1 + accF[i][2] * wl2 + accF[i][3] * wl3;
            float pr = accF[i][0] * wr0 + accF[i][1] * wr1 + accF[i][2] * wr2 + accF[i][3] * wr3;
            atomicAdd(&ssl[rb + i], pl);
            atomicAdd(&ssr[rb + i], pr);
        }
    }
    __syncthreads();
    if (tid < 64) {
        int gr = row0 + tid;
        if (gr < NN) {
            g_sdst[gr] = ssl[tid];
            g_ssrc[gr] = ssr[tid];
        }
    }
}

// ---------------------------------------------------------------------------
// CSR row pointers via binary search (edge_dst is sorted)
__global__ void k_rowptr(const int* __restrict__ dst) {
    int n = blockIdx.x * blockDim.x + threadIdx.x;
    if (n > NN) return;
    int lo = 0, hi = EE;
    while (lo < hi) {
        int mid = (lo + hi) >> 1;
        if (dst[mid] < n) lo = mid + 1;
        else hi = mid;
    }
    g_rowptr[n] = lo;
}

// ---------------------------------------------------------------------------
// score[e] = leaky_relu(s_dst[dst] + s_src[src])
__global__ void k_score(const int* __restrict__ src, const int* __restrict__ dst) {
    int e = blockIdx.x * blockDim.x + threadIdx.x;
    if (e >= EE) return;
    float v = g_sdst[dst[e]] + g_ssrc[src[e]];
    g_score[e] = v > 0.f ? v : 0.01f * v;
}

// ---------------------------------------------------------------------------
// One warp per destination node:
//   pass 1: m = max score over segment
//   pass 2: denom += exp(s-m); acc += exp(s-m) * ft[src]   (softmax is linear)
//   epilogue: out = elu(res + acc/denom)
__global__ void __launch_bounds__(256) k_agg(const int* __restrict__ src, float* __restrict__ out) {
    int warp = (blockIdx.x * blockDim.x + threadIdx.x) >> 5;
    int lane = threadIdx.x & 31;
    if (warp >= NN) return;

    int s0 = g_rowptr[warp];
    int s1 = g_rowptr[warp + 1];

    float m = -3.402823e38f;
    for (int e = s0 + lane; e < s1; e += 32) m = fmaxf(m, g_score[e]);
#pragma unroll
    for (int o = 16; o > 0; o >>= 1) m = fmaxf(m, __shfl_xor_sync(0xffffffffu, m, o));

    float acc0 = 0.f, acc1 = 0.f, den = 0.f;
    const float2* __restrict__ ft2 = (const float2*)g_ft;
    for (int e0 = s0; e0 < s1; e0 += 32) {
        int e = e0 + lane;
        float ex = 0.f;
        int sr = 0;
        if (e < s1) {
            ex = expf(g_score[e] - m);
            sr = src[e];
        }
        den += ex;
        int cnt = min(32, s1 - e0);
        for (int j = 0; j < cnt; j++) {
            float exj = __shfl_sync(0xffffffffu, ex, j);
            int srj = __shfl_sync(0xffffffffu, sr, j);
            // row srj: 64 floats = 32 float2; lane reads float2 -> dims (2*lane, 2*lane+1)
            float2 v = ft2[srj * 32 + lane];
            acc0 += exj * v.x;
            acc1 += exj * v.y;
        }
    }
#pragma unroll
    for (int o = 16; o > 0; o >>= 1) den += __shfl_xor_sync(0xffffffffu, den, o);
    if (den == 0.f) den = 1.f;
    float inv = 1.f / den;

    int base = warp * 64;
    int c0 = 2 * lane, c1 = 2 * lane + 1;
    float v0 = g_res[base + c0] + acc0 * inv;
    float v1 = g_res[base + c1] + acc1 * inv;
    out[base + c0] = v0 > 0.f ? v0 : expm1f(v0);
    out[base + c1] = v1 > 0.f ? v1 : expm1f(v1);
}

// ---------------------------------------------------------------------------
extern "C" void kernel_launch(void* const* d_in, const int* in_sizes, int n_in,
                              void* d_out, int out_size) {
    const float* feats = (const float*)d_in[0];
    const float* Wfc   = (const float*)d_in[1];
    const float* Wl    = (const float*)d_in[2];
    const float* Wr    = (const float*)d_in[3];
    const float* Wres  = (const float*)d_in[4];
    const int* esrc    = (const int*)d_in[5];
    const int* edst    = (const int*)d_in[6];
    float* out = (float*)d_out;

    k_vec<<<1, 64>>>(Wl, Wr);
    k_gemm<<<(NN + 63) / 64, 256>>>(feats, Wfc, Wres);
    k_rowptr<<<(NN + 1 + 255) / 256, 256>>>(edst);
    k_score<<<(EE + 255) / 256, 256>>>(esrc, edst);
    k_agg<<<(NN * 32 + 255) / 256, 256>>>(esrc, out);
}

// round 7
// speedup vs baseline: 1.3795x; 1.3795x over previous
#include <cuda_runtime.h>
#include <cuda_bf16.h>
#include <cstdint>

#define NN 100000
#define EE 1600000
#define IND 128
#define HID 64
#define MTILE 128
#define NBLK ((NN + MTILE - 1) / MTILE)
#define KCH 64
#define ROWP 68   // padded smem row length (bf16 elems) -> 136B, breaks bank alignment

// scratch (static device globals; allocation-free)
__device__ float g_ft[NN * HID];
__device__ float g_res[NN * HID];
__device__ float g_sdst[NN];
__device__ float g_ssrc[NN];
__device__ int   g_rowptr[NN + 1];
__device__ float g_wl[HID];
__device__ float g_wr[HID];
// B operand [N=128][K=128]: n<64 = W_fc col n, n>=64 = W_res col n-64; hi/lo bf16 split
__device__ __nv_bfloat16 g_Bhi[128 * 128];
__device__ __nv_bfloat16 g_Blo[128 * 128];

// ---------------------------------------------------------------------------
#define MMA_BF16(c, a, b0, b1) \
    asm volatile("mma.sync.aligned.m16n8k16.row.col.f32.bf16.bf16.f32 " \
        "{%0,%1,%2,%3}, {%4,%5,%6,%7}, {%8,%9}, {%0,%1,%2,%3};" \
        : "+f"((c)[0]), "+f"((c)[1]), "+f"((c)[2]), "+f"((c)[3]) \
        : "r"((a)[0]), "r"((a)[1]), "r"((a)[2]), "r"((a)[3]), "r"(b0), "r"(b1))

// ---------------------------------------------------------------------------
// wl[h] = sum_a W_l[h][a]  (scores sum over attention dim -> vector dot)
__global__ void k_vec(const float* __restrict__ Wl, const float* __restrict__ Wr) {
    int t = threadIdx.x;  // 64
    float sl = 0.f, sr = 0.f;
#pragma unroll
    for (int a = 0; a < 64; a++) { sl += Wl[t * 64 + a]; sr += Wr[t * 64 + a]; }
    g_wl[t] = sl; g_wr[t] = sr;
}

// ---------------------------------------------------------------------------
// Build B operand (transposed, hi/lo bf16 split): B[n][k] = W[k][n]
__global__ void k_prepB(const float* __restrict__ Wfc, const float* __restrict__ Wres) {
    int n = blockIdx.x;   // 0..127
    int k = threadIdx.x;  // 0..127
    float v = (n < 64) ? Wfc[k * 64 + n] : Wres[k * 64 + (n - 64)];
    __nv_bfloat16 h = __float2bfloat16(v);
    g_Bhi[n * 128 + k] = h;
    g_Blo[n * 128 + k] = __float2bfloat16(v - __bfloat162float(h));
}

// ---------------------------------------------------------------------------
// HMMA fused double GEMM with 3xbf16 split for fp32 accuracy.
// CTA: M=128 x N=128 ([ft|res]) x K=128 in two K=64 chunks. 256 threads = 8 warps.
// Warp tile 32(M)x64(N): 2 m-tiles (m16) x 8 n-tiles (n8), mma.m16n8k16.
// SMEM per chunk: Ahi/Alo/Bhi/Blo [128][68] bf16 = 17408 B each.
#define AHI_OFF 0
#define ALO_OFF 17408
#define BHI_OFF 34816
#define BLO_OFF 52224
#define DYN_BYTES 69632
__global__ void __launch_bounds__(256) k_gemm_mma(const float* __restrict__ feats) {
    extern __shared__ __align__(16) char sm[];
    __shared__ float s_wl[64], s_wr[64];
    __nv_bfloat16* Ahi = (__nv_bfloat16*)(sm + AHI_OFF);
    __nv_bfloat16* Alo = (__nv_bfloat16*)(sm + ALO_OFF);
    __nv_bfloat16* Bhi = (__nv_bfloat16*)(sm + BHI_OFF);
    __nv_bfloat16* Blo = (__nv_bfloat16*)(sm + BLO_OFF);

    int tid = threadIdx.x;
    int wid = tid >> 5, lane = tid & 31;
    int g = lane >> 2, t = lane & 3;
    int warpM = wid >> 1, warpN = wid & 1;
    int mbase = warpM * 32, nbase = warpN * 64;
    if (tid < 64) { s_wl[tid] = g_wl[tid]; s_wr[tid] = g_wr[tid]; }

    int m0 = blockIdx.x * MTILE;
    int rowlim = NN - m0;

    float acc[2][8][4];
#pragma unroll
    for (int mt = 0; mt < 2; mt++)
#pragma unroll
        for (int nt = 0; nt < 8; nt++)
#pragma unroll
            for (int q = 0; q < 4; q++) acc[mt][nt][q] = 0.f;

    const uint32_t* bhig = (const uint32_t*)g_Bhi;  // row length 64 u32
    const uint32_t* blog = (const uint32_t*)g_Blo;

    for (int kc = 0; kc < IND; kc += KCH) {
        // ---- load A chunk (fp32 -> hi/lo bf16) and B chunk (prebuilt bf16) ----
#pragma unroll 4
        for (int i = 0; i < 16; i++) {
            int p = tid + i * 256;      // 0..4095
            int r = p >> 5;             // row / n, 0..127
            int cp = p & 31;            // col-pair within chunk (cols 2cp, 2cp+1)
            float2 v = (r < rowlim) ? *(const float2*)&feats[(size_t)(m0 + r) * IND + kc + 2 * cp]
                                    : make_float2(0.f, 0.f);
            __nv_bfloat162 h2 = __floats2bfloat162_rn(v.x, v.y);
            __nv_bfloat162 l2 = __floats2bfloat162_rn(v.x - __bfloat162float(h2.x),
                                                      v.y - __bfloat162float(h2.y));
            *(__nv_bfloat162*)&Ahi[r * ROWP + 2 * cp] = h2;
            *(__nv_bfloat162*)&Alo[r * ROWP + 2 * cp] = l2;
            uint32_t bh = bhig[r * 64 + (kc >> 1) + cp];
            uint32_t bl = blog[r * 64 + (kc >> 1) + cp];
            *(uint32_t*)&Bhi[r * ROWP + 2 * cp] = bh;
            *(uint32_t*)&Blo[r * ROWP + 2 * cp] = bl;
        }
        __syncthreads();

        // ---- mma over 4 k-steps of 16 ----
#pragma unroll
        for (int ks = 0; ks < 4; ks++) {
            int k0 = ks * 16;
            uint32_t aH[2][4], aL[2][4];
#pragma unroll
            for (int mt = 0; mt < 2; mt++) {
                int row = mbase + mt * 16 + g;
                int base = row * ROWP + k0 + 2 * t;
                aH[mt][0] = *(const uint32_t*)&Ahi[base];
                aH[mt][1] = *(const uint32_t*)&Ahi[base + 8 * ROWP];
                aH[mt][2] = *(const uint32_t*)&Ahi[base + 8];
                aH[mt][3] = *(const uint32_t*)&Ahi[base + 8 * ROWP + 8];
                aL[mt][0] = *(const uint32_t*)&Alo[base];
                aL[mt][1] = *(const uint32_t*)&Alo[base + 8 * ROWP];
                aL[mt][2] = *(const uint32_t*)&Alo[base + 8];
                aL[mt][3] = *(const uint32_t*)&Alo[base + 8 * ROWP + 8];
            }
#pragma unroll
            for (int nt = 0; nt < 8; nt++) {
                int n = nbase + nt * 8 + g;
                int bb = n * ROWP + k0 + 2 * t;
                uint32_t bH0 = *(const uint32_t*)&Bhi[bb];
                uint32_t bH1 = *(const uint32_t*)&Bhi[bb + 8];
                uint32_t bL0 = *(const uint32_t*)&Blo[bb];
                uint32_t bL1 = *(const uint32_t*)&Blo[bb + 8];
#pragma unroll
                for (int mt = 0; mt < 2; mt++) {
                    MMA_BF16(acc[mt][nt], aH[mt], bH0, bH1);
                    MMA_BF16(acc[mt][nt], aL[mt], bH0, bH1);
                    MMA_BF16(acc[mt][nt], aH[mt], bL0, bL1);
                }
            }
        }
        __syncthreads();
    }

    // ---- sdst/ssrc from fragments (warps covering cols 0..63 = ft) ----
    if (warpN == 0) {
        float pl[2][2] = {}, pr[2][2] = {};
#pragma unroll
        for (int mt = 0; mt < 2; mt++)
#pragma unroll
            for (int nt = 0; nt < 8; nt++) {
                int col = nt * 8 + 2 * t;
                float wl0 = s_wl[col], wl1 = s_wl[col + 1];
                float wr0 = s_wr[col], wr1 = s_wr[col + 1];
                pl[mt][0] += acc[mt][nt][0] * wl0 + acc[mt][nt][1] * wl1;
                pl[mt][1] += acc[mt][nt][2] * wl0 + acc[mt][nt][3] * wl1;
                pr[mt][0] += acc[mt][nt][0] * wr0 + acc[mt][nt][1] * wr1;
                pr[mt][1] += acc[mt][nt][2] * wr0 + acc[mt][nt][3] * wr1;
            }
#pragma unroll
        for (int off = 1; off <= 2; off <<= 1) {
#pragma unroll
            for (int mt = 0; mt < 2; mt++)
#pragma unroll
                for (int h = 0; h < 2; h++) {
                    pl[mt][h] += __shfl_xor_sync(0xffffffffu, pl[mt][h], off);
                    pr[mt][h] += __shfl_xor_sync(0xffffffffu, pr[mt][h], off);
                }
        }
        if (t == 0) {
#pragma unroll
            for (int mt = 0; mt < 2; mt++)
#pragma unroll
                for (int h = 0; h < 2; h++) {
                    int m = m0 + mbase + mt * 16 + g + h * 8;
                    if (m < NN) { g_sdst[m] = pl[mt][h]; g_ssrc[m] = pr[mt][h]; }
                }
        }
    }

    // ---- stage C in smem (reuse tiles; fragments are in regs), then coalesce out ----
    float* stage = (float*)sm;  // [128][132]
#pragma unroll
    for (int mt = 0; mt < 2; mt++)
#pragma unroll
        for (int nt = 0; nt < 8; nt++) {
            int row = mbase + mt * 16 + g;
            int col = nbase + nt * 8 + 2 * t;
            *(float2*)&stage[row * 132 + col] = make_float2(acc[mt][nt][0], acc[mt][nt][1]);
            *(float2*)&stage[(row + 8) * 132 + col] = make_float2(acc[mt][nt][2], acc[mt][nt][3]);
        }
    __syncthreads();

#pragma unroll 4
    for (int i = 0; i < 8; i++) {
        int p = tid + i * 256;   // 0..2047
        int r = p >> 4, c4 = p & 15;
        if (r < rowlim) {
            *(float4*)&g_ft[(size_t)(m0 + r) * 64 + c4 * 4]  = *(float4*)&stage[r * 132 + c4 * 4];
            *(float4*)&g_res[(size_t)(m0 + r) * 64 + c4 * 4] = *(float4*)&stage[r * 132 + 64 + c4 * 4];
        }
    }
}

// ---------------------------------------------------------------------------
// CSR row pointers via binary search (edge_dst is sorted)
__global__ void k_rowptr(const int* __restrict__ dst) {
    int n = blockIdx.x * blockDim.x + threadIdx.x;
    if (n > NN) return;
    int lo = 0, hi = EE;
    while (lo < hi) {
        int mid = (lo + hi) >> 1;
        if (dst[mid] < n) lo = mid + 1;
        else hi = mid;
    }
    g_rowptr[n] = lo;
}

// ---------------------------------------------------------------------------
// One warp per destination node. Score fused (leaky_relu recomputed per pass):
//   pass 1: m = max over segment of lrelu(sdst + ssrc[src])
//   pass 2: denom += exp(s-m); acc += exp(s-m) * ft[src]
//   out = elu(res + acc/denom)
__global__ void __launch_bounds__(256) k_agg(const int* __restrict__ src, float* __restrict__ out) {
    int warp = (blockIdx.x * blockDim.x + threadIdx.x) >> 5;
    int lane = threadIdx.x & 31;
    if (warp >= NN) return;

    int s0 = g_rowptr[warp];
    int s1 = g_rowptr[warp + 1];
    float sd = g_sdst[warp];

    float m = -3.402823e38f;
    for (int e = s0 + lane; e < s1; e += 32) {
        float s = sd + g_ssrc[src[e]];
        s = s > 0.f ? s : 0.01f * s;
        m = fmaxf(m, s);
    }
#pragma unroll
    for (int o = 16; o > 0; o >>= 1) m = fmaxf(m, __shfl_xor_sync(0xffffffffu, m, o));

    float acc0 = 0.f, acc1 = 0.f, den = 0.f;
    const float2* __restrict__ ft2 = (const float2*)g_ft;
    for (int e0 = s0; e0 < s1; e0 += 32) {
        int e = e0 + lane;
        float ex = 0.f;
        int sr = 0;
        if (e < s1) {
            sr = src[e];
            float s = sd + g_ssrc[sr];
            s = s > 0.f ? s : 0.01f * s;
            ex = expf(s - m);
        }
        den += ex;
        int cnt = min(32, s1 - e0);
#pragma unroll 4
        for (int j = 0; j < cnt; j++) {
            float exj = __shfl_sync(0xffffffffu, ex, j);
            int srj = __shfl_sync(0xffffffffu, sr, j);
            float2 v = ft2[srj * 32 + lane];
            acc0 += exj * v.x;
            acc1 += exj * v.y;
        }
    }
#pragma unroll
    for (int o = 16; o > 0; o >>= 1) den += __shfl_xor_sync(0xffffffffu, den, o);
    if (den == 0.f) den = 1.f;
    float inv = 1.f / den;

    int base = warp * 64;
    int c0 = 2 * lane, c1 = 2 * lane + 1;
    float v0 = g_res[base + c0] + acc0 * inv;
    float v1 = g_res[base + c1] + acc1 * inv;
    out[base + c0] = v0 > 0.f ? v0 : expm1f(v0);
    out[base + c1] = v1 > 0.f ? v1 : expm1f(v1);
}

// ---------------------------------------------------------------------------
extern "C" void kernel_launch(void* const* d_in, const int* in_sizes, int n_in,
                              void* d_out, int out_size) {
    const float* feats = (const float*)d_in[0];
    const float* Wfc   = (const float*)d_in[1];
    const float* Wl    = (const float*)d_in[2];
    const float* Wr    = (const float*)d_in[3];
    const float* Wres  = (const float*)d_in[4];
    const int* esrc    = (const int*)d_in[5];
    const int* edst    = (const int*)d_in[6];
    float* out = (float*)d_out;

    cudaFuncSetAttribute(k_gemm_mma, cudaFuncAttributeMaxDynamicSharedMemorySize, DYN_BYTES);

    k_vec<<<1, 64>>>(Wl, Wr);
    k_prepB<<<128, 128>>>(Wfc, Wres);
    k_gemm_mma<<<NBLK, 256, DYN_BYTES>>>(feats);
    k_rowptr<<<(NN + 1 + 255) / 256, 256>>>(edst);
    k_agg<<<(NN * 32 + 255) / 256, 256>>>(esrc, out);
}

// round 9
// speedup vs baseline: 1.4339x; 1.0395x over previous
#include <cuda_runtime.h>
#include <cuda_bf16.h>
#include <cstdint>

#define NN 100000
#define EE 1600000
#define IND 128
#define HID 64
#define MTILE 128
#define NBLK ((NN + MTILE - 1) / MTILE)
#define KCH 64
#define ROWP 68   // padded smem row length (bf16 elems) -> 136B, breaks bank alignment

// scratch (static device globals; allocation-free)
__device__ float g_ft[NN * HID];
__device__ float g_res[NN * HID];
__device__ float g_sdst[NN];
__device__ float g_ssrc[NN];
__device__ int   g_rowptr[NN + 1];
__device__ float g_wl[HID];
__device__ float g_wr[HID];
// B operand [N=128][K=128]: n<64 = W_fc col n, n>=64 = W_res col n-64; hi/lo bf16 split
__device__ __nv_bfloat16 g_Bhi[128 * 128];
__device__ __nv_bfloat16 g_Blo[128 * 128];

// ---------------------------------------------------------------------------
#define MMA_BF16(c, a, b0, b1) \
    asm volatile("mma.sync.aligned.m16n8k16.row.col.f32.bf16.bf16.f32 " \
        "{%0,%1,%2,%3}, {%4,%5,%6,%7}, {%8,%9}, {%0,%1,%2,%3};" \
        : "+f"((c)[0]), "+f"((c)[1]), "+f"((c)[2]), "+f"((c)[3]) \
        : "r"((a)[0]), "r"((a)[1]), "r"((a)[2]), "r"((a)[3]), "r"(b0), "r"(b1))

// ---------------------------------------------------------------------------
// wl[h] = sum_a W_l[h][a]  (scores sum over attention dim -> vector dot)
__global__ void k_vec(const float* __restrict__ Wl, const float* __restrict__ Wr) {
    int t = threadIdx.x;  // 64
    float sl = 0.f, sr = 0.f;
#pragma unroll
    for (int a = 0; a < 64; a++) { sl += Wl[t * 64 + a]; sr += Wr[t * 64 + a]; }
    g_wl[t] = sl; g_wr[t] = sr;
}

// ---------------------------------------------------------------------------
// Build B operand (transposed, hi/lo bf16 split): B[n][k] = W[k][n]
__global__ void k_prepB(const float* __restrict__ Wfc, const float* __restrict__ Wres) {
    int n = blockIdx.x;   // 0..127
    int k = threadIdx.x;  // 0..127
    float v = (n < 64) ? Wfc[k * 64 + n] : Wres[k * 64 + (n - 64)];
    __nv_bfloat16 h = __float2bfloat16(v);
    g_Bhi[n * 128 + k] = h;
    g_Blo[n * 128 + k] = __float2bfloat16(v - __bfloat162float(h));
}

// ---------------------------------------------------------------------------
// HMMA fused double GEMM with 3xbf16 split for fp32 accuracy.
// CTA: M=128 x N=128 ([ft|res]) x K=128 in two K=64 chunks. 256 threads = 8 warps.
// Warp tile 32(M)x64(N): 2 m-tiles (m16) x 8 n-tiles (n8), mma.m16n8k16.
// SMEM per chunk: Ahi/Alo/Bhi/Blo [128][68] bf16 = 17408 B each.
#define AHI_OFF 0
#define ALO_OFF 17408
#define BHI_OFF 34816
#define BLO_OFF 52224
#define DYN_BYTES 69632
__global__ void __launch_bounds__(256) k_gemm_mma(const float* __restrict__ feats) {
    extern __shared__ __align__(16) char sm[];
    __shared__ float s_wl[64], s_wr[64];
    __nv_bfloat16* Ahi = (__nv_bfloat16*)(sm + AHI_OFF);
    __nv_bfloat16* Alo = (__nv_bfloat16*)(sm + ALO_OFF);
    __nv_bfloat16* Bhi = (__nv_bfloat16*)(sm + BHI_OFF);
    __nv_bfloat16* Blo = (__nv_bfloat16*)(sm + BLO_OFF);

    int tid = threadIdx.x;
    int wid = tid >> 5, lane = tid & 31;
    int g = lane >> 2, t = lane & 3;
    int warpM = wid >> 1, warpN = wid & 1;
    int mbase = warpM * 32, nbase = warpN * 64;
    if (tid < 64) { s_wl[tid] = g_wl[tid]; s_wr[tid] = g_wr[tid]; }

    int m0 = blockIdx.x * MTILE;
    int rowlim = NN - m0;

    float acc[2][8][4];
#pragma unroll
    for (int mt = 0; mt < 2; mt++)
#pragma unroll
        for (int nt = 0; nt < 8; nt++)
#pragma unroll
            for (int q = 0; q < 4; q++) acc[mt][nt][q] = 0.f;

    const uint32_t* bhig = (const uint32_t*)g_Bhi;  // row length 64 u32
    const uint32_t* blog = (const uint32_t*)g_Blo;

    for (int kc = 0; kc < IND; kc += KCH) {
        // ---- load A chunk (fp32 -> hi/lo bf16) and B chunk (prebuilt bf16) ----
#pragma unroll 4
        for (int i = 0; i < 16; i++) {
            int p = tid + i * 256;      // 0..4095
            int r = p >> 5;             // row / n, 0..127
            int cp = p & 31;            // col-pair within chunk (cols 2cp, 2cp+1)
            float2 v = (r < rowlim) ? *(const float2*)&feats[(size_t)(m0 + r) * IND + kc + 2 * cp]
                                    : make_float2(0.f, 0.f);
            __nv_bfloat162 h2 = __floats2bfloat162_rn(v.x, v.y);
            __nv_bfloat162 l2 = __floats2bfloat162_rn(v.x - __bfloat162float(h2.x),
                                                      v.y - __bfloat162float(h2.y));
            *(__nv_bfloat162*)&Ahi[r * ROWP + 2 * cp] = h2;
            *(__nv_bfloat162*)&Alo[r * ROWP + 2 * cp] = l2;
            uint32_t bh = bhig[r * 64 + (kc >> 1) + cp];
            uint32_t bl = blog[r * 64 + (kc >> 1) + cp];
            *(uint32_t*)&Bhi[r * ROWP + 2 * cp] = bh;
            *(uint32_t*)&Blo[r * ROWP + 2 * cp] = bl;
        }
        __syncthreads();

        // ---- mma over 4 k-steps of 16 ----
#pragma unroll
        for (int ks = 0; ks < 4; ks++) {
            int k0 = ks * 16;
            uint32_t aH[2][4], aL[2][4];
#pragma unroll
            for (int mt = 0; mt < 2; mt++) {
                int row = mbase + mt * 16 + g;
                int base = row * ROWP + k0 + 2 * t;
                aH[mt][0] = *(const uint32_t*)&Ahi[base];
                aH[mt][1] = *(const uint32_t*)&Ahi[base + 8 * ROWP];
                aH[mt][2] = *(const uint32_t*)&Ahi[base + 8];
                aH[mt][3] = *(const uint32_t*)&Ahi[base + 8 * ROWP + 8];
                aL[mt][0] = *(const uint32_t*)&Alo[base];
                aL[mt][1] = *(const uint32_t*)&Alo[base + 8 * ROWP];
                aL[mt][2] = *(const uint32_t*)&Alo[base + 8];
                aL[mt][3] = *(const uint32_t*)&Alo[base + 8 * ROWP + 8];
            }
#pragma unroll
            for (int nt = 0; nt < 8; nt++) {
                int n = nbase + nt * 8 + g;
                int bb = n * ROWP + k0 + 2 * t;
                uint32_t bH0 = *(const uint32_t*)&Bhi[bb];
                uint32_t bH1 = *(const uint32_t*)&Bhi[bb + 8];
                uint32_t bL0 = *(const uint32_t*)&Blo[bb];
                uint32_t bL1 = *(const uint32_t*)&Blo[bb + 8];
#pragma unroll
                for (int mt = 0; mt < 2; mt++) {
                    MMA_BF16(acc[mt][nt], aH[mt], bH0, bH1);
                    MMA_BF16(acc[mt][nt], aL[mt], bH0, bH1);
                    MMA_BF16(acc[mt][nt], aH[mt], bL0, bL1);
                }
            }
        }
        __syncthreads();
    }

    // ---- sdst/ssrc from fragments (warps covering cols 0..63 = ft) ----
    if (warpN == 0) {
        float pl[2][2] = {}, pr[2][2] = {};
#pragma unroll
        for (int mt = 0; mt < 2; mt++)
#pragma unroll
            for (int nt = 0; nt < 8; nt++) {
                int col = nt * 8 + 2 * t;
                float wl0 = s_wl[col], wl1 = s_wl[col + 1];
                float wr0 = s_wr[col], wr1 = s_wr[col + 1];
                pl[mt][0] += acc[mt][nt][0] * wl0 + acc[mt][nt][1] * wl1;
                pl[mt][1] += acc[mt][nt][2] * wl0 + acc[mt][nt][3] * wl1;
                pr[mt][0] += acc[mt][nt][0] * wr0 + acc[mt][nt][1] * wr1;
                pr[mt][1] += acc[mt][nt][2] * wr0 + acc[mt][nt][3] * wr1;
            }
#pragma unroll
        for (int off = 1; off <= 2; off <<= 1) {
#pragma unroll
            for (int mt = 0; mt < 2; mt++)
#pragma unroll
                for (int h = 0; h < 2; h++) {
                    pl[mt][h] += __shfl_xor_sync(0xffffffffu, pl[mt][h], off);
                    pr[mt][h] += __shfl_xor_sync(0xffffffffu, pr[mt][h], off);
                }
        }
        if (t == 0) {
#pragma unroll
            for (int mt = 0; mt < 2; mt++)
#pragma unroll
                for (int h = 0; h < 2; h++) {
                    int m = m0 + mbase + mt * 16 + g + h * 8;
                    if (m < NN) { g_sdst[m] = pl[mt][h]; g_ssrc[m] = pr[mt][h]; }
                }
        }
    }

    // ---- stage C in smem (reuse tiles; fragments are in regs), then coalesce out ----
    float* stage = (float*)sm;  // [128][132]
#pragma unroll
    for (int mt = 0; mt < 2; mt++)
#pragma unroll
        for (int nt = 0; nt < 8; nt++) {
            int row = mbase + mt * 16 + g;
            int col = nbase + nt * 8 + 2 * t;
            *(float2*)&stage[row * 132 + col] = make_float2(acc[mt][nt][0], acc[mt][nt][1]);
            *(float2*)&stage[(row + 8) * 132 + col] = make_float2(acc[mt][nt][2], acc[mt][nt][3]);
        }
    __syncthreads();

#pragma unroll 4
    for (int i = 0; i < 8; i++) {
        int p = tid + i * 256;   // 0..2047
        int r = p >> 4, c4 = p & 15;
        if (r < rowlim) {
            *(float4*)&g_ft[(size_t)(m0 + r) * 64 + c4 * 4]  = *(float4*)&stage[r * 132 + c4 * 4];
            *(float4*)&g_res[(size_t)(m0 + r) * 64 + c4 * 4] = *(float4*)&stage[r * 132 + 64 + c4 * 4];
        }
    }
}

// ---------------------------------------------------------------------------
// CSR row pointers via boundary diff (edge_dst sorted): thread e fills
// rowptr[n] = e for all n in (dst[e-1], dst[e]]. Streaming, no search.
__global__ void k_rowptr(const int* __restrict__ dst) {
    int e = blockIdx.x * blockDim.x + threadIdx.x;
    if (e >= EE) return;
    int cur = dst[e];
    int prev = (e == 0) ? -1 : dst[e - 1];
    for (int n = prev + 1; n <= cur; n++) g_rowptr[n] = e;
    if (e == EE - 1) {
        for (int n = cur + 1; n <= NN; n++) g_rowptr[n] = EE;
    }
}

// ---------------------------------------------------------------------------
// One warp per destination node, SINGLE pass (online softmax):
//   per 32-edge chunk: s = lrelu(sdst + ssrc[src]); chunk max; rescale acc/den;
//   den += exp(s-m); acc += exp(s-m) * ft[src]
//   out = elu(res + acc/den)
__global__ void __launch_bounds__(256) k_agg(const int* __restrict__ src, float* __restrict__ out) {
    int warp = (blockIdx.x * blockDim.x + threadIdx.x) >> 5;
    int lane = threadIdx.x & 31;
    if (warp >= NN) return;

    int s0 = g_rowptr[warp];
    int s1 = g_rowptr[warp + 1];
    float sd = g_sdst[warp];

    float m = -3.402823e38f;
    float acc0 = 0.f, acc1 = 0.f, den = 0.f;
    const float2* __restrict__ ft2 = (const float2*)g_ft;

    for (int e0 = s0; e0 < s1; e0 += 32) {
        int e = e0 + lane;
        float s = -3.402823e38f;
        int sr = 0;
        if (e < s1) {
            sr = src[e];
            s = sd + g_ssrc[sr];
            s = s > 0.f ? s : 0.01f * s;
        }
        // chunk max -> new running max
        float cm = s;
#pragma unroll
        for (int o = 16; o > 0; o >>= 1) cm = fmaxf(cm, __shfl_xor_sync(0xffffffffu, cm, o));
        float newm = fmaxf(m, cm);
        float scale = expf(m - newm);   // first chunk: exp(-inf)=0, acc/den are 0 anyway
        acc0 *= scale; acc1 *= scale; den *= scale;
        m = newm;

        float ex = (e < s1) ? expf(s - m) : 0.f;
        den += ex;
        int cnt = min(32, s1 - e0);
#pragma unroll 4
        for (int j = 0; j < cnt; j++) {
            float exj = __shfl_sync(0xffffffffu, ex, j);
            int srj = __shfl_sync(0xffffffffu, sr, j);
            float2 v = ft2[srj * 32 + lane];
            acc0 += exj * v.x;
            acc1 += exj * v.y;
        }
    }
#pragma unroll
    for (int o = 16; o > 0; o >>= 1) den += __shfl_xor_sync(0xffffffffu, den, o);
    if (den == 0.f) den = 1.f;
    float inv = 1.f / den;

    int base = warp * 64;
    int c0 = 2 * lane, c1 = 2 * lane + 1;
    float v0 = g_res[base + c0] + acc0 * inv;
    float v1 = g_res[base + c1] + acc1 * inv;
    out[base + c0] = v0 > 0.f ? v0 : expm1f(v0);
    out[base + c1] = v1 > 0.f ? v1 : expm1f(v1);
}

// ---------------------------------------------------------------------------
extern "C" void kernel_launch(void* const* d_in, const int* in_sizes, int n_in,
                              void* d_out, int out_size) {
    const float* feats = (const float*)d_in[0];
    const float* Wfc   = (const float*)d_in[1];
    const float* Wl    = (const float*)d_in[2];
    const float* Wr    = (const float*)d_in[3];
    const float* Wres  = (const float*)d_in[4];
    const int* esrc    = (const int*)d_in[5];
    const int* edst    = (const int*)d_in[6];
    float* out = (float*)d_out;

    cudaFuncSetAttribute(k_gemm_mma, cudaFuncAttributeMaxDynamicSharedMemorySize, DYN_BYTES);

    k_vec<<<1, 64>>>(Wl, Wr);
    k_prepB<<<128, 128>>>(Wfc, Wres);
    k_gemm_mma<<<NBLK, 256, DYN_BYTES>>>(feats);
    k_rowptr<<<(EE + 255) / 256, 256>>>(edst);
    k_agg<<<(NN * 32 + 255) / 256, 256>>>(esrc, out);
}

// round 12
// speedup vs baseline: 1.5985x; 1.1148x over previous
#include <cuda_runtime.h>
#include <cuda_bf16.h>
#include <cstdint>

#define NN 100000
#define EE 1600000
#define IND 128
#define HID 64
#define MTILE 128
#define NBLK ((NN + MTILE - 1) / MTILE)
#define KCH 64
#define ROWP 68   // padded smem row length (bf16 elems) -> 136B

// scratch (static device globals; allocation-free)
__device__ float g_ft[NN * HID];
__device__ float g_res[NN * HID];
__device__ float g_sdst[NN];
__device__ float g_ssrc[NN];
__device__ int   g_rowptr[NN + 1];
__device__ float g_wl[HID];
__device__ float g_wr[HID];
// B operand [N=128][K=128]: n<64 = W_fc col n, n>=64 = W_res col n-64; hi/lo bf16 split
__device__ __nv_bfloat16 g_Bhi[128 * 128];
__device__ __nv_bfloat16 g_Blo[128 * 128];

// ---------------------------------------------------------------------------
#define MMA_BF16(c, a, b0, b1) \
    asm volatile("mma.sync.aligned.m16n8k16.row.col.f32.bf16.bf16.f32 " \
        "{%0,%1,%2,%3}, {%4,%5,%6,%7}, {%8,%9}, {%0,%1,%2,%3};" \
        : "+f"((c)[0]), "+f"((c)[1]), "+f"((c)[2]), "+f"((c)[3]) \
        : "r"((a)[0]), "r"((a)[1]), "r"((a)[2]), "r"((a)[3]), "r"(b0), "r"(b1))

// ---------------------------------------------------------------------------
// Blocks 0..127: build B operand (transposed, hi/lo bf16 split) B[n][k] = W[k][n].
// Block 128: wl[h] = sum_a W_l[h][a], wr likewise.
__global__ void k_prep(const float* __restrict__ Wfc, const float* __restrict__ Wres,
                       const float* __restrict__ Wl, const float* __restrict__ Wr) {
    if (blockIdx.x == 128) {
        int t = threadIdx.x;
        if (t < 64) {
            float sl = 0.f, sr = 0.f;
#pragma unroll
            for (int a = 0; a < 64; a++) { sl += Wl[t * 64 + a]; sr += Wr[t * 64 + a]; }
            g_wl[t] = sl; g_wr[t] = sr;
        }
        return;
    }
    int n = blockIdx.x;   // 0..127
    int k = threadIdx.x;  // 0..127
    float v = (n < 64) ? Wfc[k * 64 + n] : Wres[k * 64 + (n - 64)];
    __nv_bfloat16 h = __float2bfloat16(v);
    g_Bhi[n * 128 + k] = h;
    g_Blo[n * 128 + k] = __float2bfloat16(v - __bfloat162float(h));
}

// ---------------------------------------------------------------------------
// HMMA fused double GEMM with 3xbf16 split for fp32 accuracy.
// CTA: M=128 x N=128 ([ft|res]) x K=128 in two K=64 chunks. 256 threads = 8 warps.
#define AHI_OFF 0
#define ALO_OFF 17408
#define BHI_OFF 34816
#define BLO_OFF 52224
#define DYN_BYTES 69632
__global__ void __launch_bounds__(256) k_gemm_mma(const float* __restrict__ feats) {
    extern __shared__ __align__(16) char sm[];
    __shared__ float s_wl[64], s_wr[64];
    __nv_bfloat16* Ahi = (__nv_bfloat16*)(sm + AHI_OFF);
    __nv_bfloat16* Alo = (__nv_bfloat16*)(sm + ALO_OFF);
    __nv_bfloat16* Bhi = (__nv_bfloat16*)(sm + BHI_OFF);
    __nv_bfloat16* Blo = (__nv_bfloat16*)(sm + BLO_OFF);

    int tid = threadIdx.x;
    int wid = tid >> 5, lane = tid & 31;
    int g = lane >> 2, t = lane & 3;
    int warpM = wid >> 1, warpN = wid & 1;
    int mbase = warpM * 32, nbase = warpN * 64;
    if (tid < 64) { s_wl[tid] = g_wl[tid]; s_wr[tid] = g_wr[tid]; }

    int m0 = blockIdx.x * MTILE;
    int rowlim = NN - m0;

    float acc[2][8][4];
#pragma unroll
    for (int mt = 0; mt < 2; mt++)
#pragma unroll
        for (int nt = 0; nt < 8; nt++)
#pragma unroll
            for (int q = 0; q < 4; q++) acc[mt][nt][q] = 0.f;

    const uint2* bhig2 = (const uint2*)g_Bhi;  // row = 32 uint2
    const uint2* blog2 = (const uint2*)g_Blo;

    for (int kc = 0; kc < IND; kc += KCH) {
        // ---- A chunk: float4 loads (fp32 -> hi/lo bf16), stored as uint2 ----
#pragma unroll
        for (int i = 0; i < 8; i++) {
            int p = tid + i * 256;      // 0..2047
            int r = p >> 4;             // row 0..127
            int q = p & 15;             // float4 idx in 64-float chunk
            float4 v = (r < rowlim) ? *(const float4*)&feats[(size_t)(m0 + r) * IND + kc + 4 * q]
                                    : make_float4(0.f, 0.f, 0.f, 0.f);
            __nv_bfloat162 h01 = __floats2bfloat162_rn(v.x, v.y);
            __nv_bfloat162 h23 = __floats2bfloat162_rn(v.z, v.w);
            __nv_bfloat162 l01 = __floats2bfloat162_rn(v.x - __bfloat162float(h01.x),
                                                       v.y - __bfloat162float(h01.y));
            __nv_bfloat162 l23 = __floats2bfloat162_rn(v.z - __bfloat162float(h23.x),
                                                       v.w - __bfloat162float(h23.y));
            uint2 hh, ll;
            hh.x = *(uint32_t*)&h01; hh.y = *(uint32_t*)&h23;
            ll.x = *(uint32_t*)&l01; ll.y = *(uint32_t*)&l23;
            *(uint2*)&Ahi[r * ROWP + 4 * q] = hh;
            *(uint2*)&Alo[r * ROWP + 4 * q] = ll;
        }
        // ---- B chunk: uint2 loads (prebuilt bf16 hi/lo) ----
#pragma unroll
        for (int i = 0; i < 8; i++) {
            int p = tid + i * 256;      // 0..2047
            int r = p >> 4;             // row/n 0..127
            int q = p & 15;             // uint2 idx in 32-u32 chunk
            uint2 bh = bhig2[r * 32 + (kc >> 2) + q];
            uint2 bl = blog2[r * 32 + (kc >> 2) + q];
            *(uint2*)&Bhi[r * ROWP + 4 * q] = bh;
            *(uint2*)&Blo[r * ROWP + 4 * q] = bl;
        }
        __syncthreads();

        // ---- mma over 4 k-steps of 16 ----
#pragma unroll
        for (int ks = 0; ks < 4; ks++) {
            int k0 = ks * 16;
            uint32_t aH[2][4], aL[2][4];
#pragma unroll
            for (int mt = 0; mt < 2; mt++) {
                int row = mbase + mt * 16 + g;
                int base = row * ROWP + k0 + 2 * t;
                aH[mt][0] = *(const uint32_t*)&Ahi[base];
                aH[mt][1] = *(const uint32_t*)&Ahi[base + 8 * ROWP];
                aH[mt][2] = *(const uint32_t*)&Ahi[base + 8];
                aH[mt][3] = *(const uint32_t*)&Ahi[base + 8 * ROWP + 8];
                aL[mt][0] = *(const uint32_t*)&Alo[base];
                aL[mt][1] = *(const uint32_t*)&Alo[base + 8 * ROWP];
                aL[mt][2] = *(const uint32_t*)&Alo[base + 8];
                aL[mt][3] = *(const uint32_t*)&Alo[base + 8 * ROWP + 8];
            }
#pragma unroll
            for (int nt = 0; nt < 8; nt++) {
                int n = nbase + nt * 8 + g;
                int bb = n * ROWP + k0 + 2 * t;
                uint32_t bH0 = *(const uint32_t*)&Bhi[bb];
                uint32_t bH1 = *(const uint32_t*)&Bhi[bb + 8];
                uint32_t bL0 = *(const uint32_t*)&Blo[bb];
                uint32_t bL1 = *(const uint32_t*)&Blo[bb + 8];
#pragma unroll
                for (int mt = 0; mt < 2; mt++) {
                    MMA_BF16(acc[mt][nt], aH[mt], bH0, bH1);
                    MMA_BF16(acc[mt][nt], aL[mt], bH0, bH1);
                    MMA_BF16(acc[mt][nt], aH[mt], bL0, bL1);
                }
            }
        }
        __syncthreads();
    }

    // ---- sdst/ssrc from fragments (warps covering cols 0..63 = ft) ----
    if (warpN == 0) {
        float pl[2][2] = {}, pr[2][2] = {};
#pragma unroll
        for (int mt = 0; mt < 2; mt++)
#pragma unroll
            for (int nt = 0; nt < 8; nt++) {
                int col = nt * 8 + 2 * t;
                float wl0 = s_wl[col], wl1 = s_wl[col + 1];
                float wr0 = s_wr[col], wr1 = s_wr[col + 1];
                pl[mt][0] += acc[mt][nt][0] * wl0 + acc[mt][nt][1] * wl1;
                pl[mt][1] += acc[mt][nt][2] * wl0 + acc[mt][nt][3] * wl1;
                pr[mt][0] += acc[mt][nt][0] * wr0 + acc[mt][nt][1] * wr1;
                pr[mt][1] += acc[mt][nt][2] * wr0 + acc[mt][nt][3] * wr1;
            }
#pragma unroll
        for (int off = 1; off <= 2; off <<= 1) {
#pragma unroll
            for (int mt = 0; mt < 2; mt++)
#pragma unroll
                for (int h = 0; h < 2; h++) {
                    pl[mt][h] += __shfl_xor_sync(0xffffffffu, pl[mt][h], off);
                    pr[mt][h] += __shfl_xor_sync(0xffffffffu, pr[mt][h], off);
                }
        }
        if (t == 0) {
#pragma unroll
            for (int mt = 0; mt < 2; mt++)
#pragma unroll
                for (int h = 0; h < 2; h++) {
                    int m = m0 + mbase + mt * 16 + g + h * 8;
                    if (m < NN) { g_sdst[m] = pl[mt][h]; g_ssrc[m] = pr[mt][h]; }
                }
        }
    }

    // ---- stage C in smem, then coalesced copy-out ----
    float* stage = (float*)sm;  // [128][132]
#pragma unroll
    for (int mt = 0; mt < 2; mt++)
#pragma unroll
        for (int nt = 0; nt < 8; nt++) {
            int row = mbase + mt * 16 + g;
            int col = nbase + nt * 8 + 2 * t;
            *(float2*)&stage[row * 132 + col] = make_float2(acc[mt][nt][0], acc[mt][nt][1]);
            *(float2*)&stage[(row + 8) * 132 + col] = make_float2(acc[mt][nt][2], acc[mt][nt][3]);
        }
    __syncthreads();

#pragma unroll
    for (int i = 0; i < 8; i++) {
        int p = tid + i * 256;   // 0..2047
        int r = p >> 4, c4 = p & 15;
        if (r < rowlim) {
            *(float4*)&g_ft[(size_t)(m0 + r) * 64 + c4 * 4]  = *(float4*)&stage[r * 132 + c4 * 4];
            *(float4*)&g_res[(size_t)(m0 + r) * 64 + c4 * 4] = *(float4*)&stage[r * 132 + 64 + c4 * 4];
        }
    }
}

// ---------------------------------------------------------------------------
// CSR row pointers: one load per thread; prev from shfl_up (lane 0 reloads).
__global__ void k_rowptr(const int* __restrict__ dst) {
    int e = blockIdx.x * blockDim.x + threadIdx.x;
    int lane = threadIdx.x & 31;
    int cur = (e < EE) ? dst[e] : 0;
    int prev = __shfl_up_sync(0xffffffffu, cur, 1);
    if (lane == 0) prev = (e == 0) ? -1 : ((e < EE) ? dst[e - 1] : 0);
    if (e < EE) {
        for (int n = prev + 1; n <= cur; n++) g_rowptr[n] = e;
        if (e == EE - 1)
            for (int n = cur + 1; n <= NN; n++) g_rowptr[n] = EE;
    }
}

// ---------------------------------------------------------------------------
// One warp per destination node, single-pass online softmax (R9-proven gather:
// each lane holds float2 of the row; 32 shuffles per chunk).
__global__ void __launch_bounds__(256) k_agg(const int* __restrict__ src, float* __restrict__ out) {
    int warp = (blockIdx.x * blockDim.x + threadIdx.x) >> 5;
    int lane = threadIdx.x & 31;
    if (warp >= NN) return;

    int s0 = g_rowptr[warp];
    int s1 = g_rowptr[warp + 1];
    float sd = g_sdst[warp];

    float m = -3.402823e38f;
    float acc0 = 0.f, acc1 = 0.f, den = 0.f;
    const float2* __restrict__ ft2 = (const float2*)g_ft;

    for (int e0 = s0; e0 < s1; e0 += 32) {
        int e = e0 + lane;
        float s = -3.402823e38f;
        int sr = 0;
        if (e < s1) {
            sr = src[e];
            s = sd + g_ssrc[sr];
            s = s > 0.f ? s : 0.01f * s;
        }
        float cm = s;
#pragma unroll
        for (int o = 16; o > 0; o >>= 1) cm = fmaxf(cm, __shfl_xor_sync(0xffffffffu, cm, o));
        float newm = fmaxf(m, cm);
        float scale = expf(m - newm);   // first chunk: exp(-inf)=0, accs are 0 anyway
        acc0 *= scale; acc1 *= scale; den *= scale;
        m = newm;

        float ex = (e < s1) ? expf(s - m) : 0.f;
        den += ex;
        int cnt = min(32, s1 - e0);
#pragma unroll 4
        for (int j = 0; j < cnt; j++) {
            float exj = __shfl_sync(0xffffffffu, ex, j);
            int srj = __shfl_sync(0xffffffffu, sr, j);
            float2 v = ft2[srj * 32 + lane];
            acc0 += exj * v.x;
            acc1 += exj * v.y;
        }
    }
#pragma unroll
    for (int o = 16; o > 0; o >>= 1) den += __shfl_xor_sync(0xffffffffu, den, o);
    if (den == 0.f) den = 1.f;
    float inv = 1.f / den;

    int base = warp * 64;
    int c0 = 2 * lane, c1 = 2 * lane + 1;
    float v0 = g_res[base + c0] + acc0 * inv;
    float v1 = g_res[base + c1] + acc1 * inv;
    out[base + c0] = v0 > 0.f ? v0 : expm1f(v0);
    out[base + c1] = v1 > 0.f ? v1 : expm1f(v1);
}

// ---------------------------------------------------------------------------
extern "C" void kernel_launch(void* const* d_in, const int* in_sizes, int n_in,
                              void* d_out, int out_size) {
    const float* feats = (const float*)d_in[0];
    const float* Wfc   = (const float*)d_in[1];
    const float* Wl    = (const float*)d_in[2];
    const float* Wr    = (const float*)d_in[3];
    const float* Wres  = (const float*)d_in[4];
    const int* esrc    = (const int*)d_in[5];
    const int* edst    = (const int*)d_in[6];
    float* out = (float*)d_out;

    cudaFuncSetAttribute(k_gemm_mma, cudaFuncAttributeMaxDynamicSharedMemorySize, DYN_BYTES);

    k_prep<<<129, 128>>>(Wfc, Wres, Wl, Wr);
    k_gemm_mma<<<NBLK, 256, DYN_BYTES>>>(feats);
    k_rowptr<<<(EE + 255) / 256, 256>>>(edst);
    k_agg<<<(NN * 32 + 255) / 256, 256>>>(esrc, out);
}